// round 10
// baseline (speedup 1.0000x reference)
#include <cuda_runtime.h>

#define N_FFT    800
#define HOP      200
#define BATCH    32
#define TLEN     480000
#define PAD      400
#define N_FRAMES 2401                 // (480800 - 800)/200 + 1
#define TS       8000                 // output tile per block
#define NF_LOC   (TS / HOP + 3)       // 43 frame positions per tile
#define NBLK     (TS / HOP + 6)       // 46 hop blocks feed those frames
#define SPAN     (TS + 1200)          // staged input: [t0-600, t0+TS+600)

#define PI_D 3.14159265358979323846

// Fully fused STFT->mag/phase->iSTFT (linear-collapse derivation, R3/R6).
//   Hann identities: win(r+400)=1-win(r), win(r+600)=1-win(r+200),
//   sum_j win(r+200j)^2 = 1.5 exactly.
//   Per hop block g: X=sum(x), A=sum(win(r)x), B=sum(win(r+200)x) (per parity).
//   S[f] = A[f] + B[f+1] + (X[f+2]-A[f+2]) + (X[f+3]-B[f+3]).
//   out = 0.75*x + (C0 + win(r)*C1 + win(r+200)*C2)/800,
//     C0=S[q-2]+S[q-3], C1=S[q]-S[q-2], C2=S[q-1]-S[q-3]  (per parity).
//   Boundary (missing frame j at edge): out -= 0.5*x*win(r+200j)^2, S:=0.
__global__ __launch_bounds__(1024, 2)
void stft_fused_kernel(const float* __restrict__ x, float* __restrict__ out) {
    __shared__ __align__(16) float sx[SPAN];        // staged (clamped) input
    __shared__ __align__(16) float sw[N_FFT];       // Hann window
    __shared__ float sX[NBLK][2], sA[NBLK][2], sB[NBLK][2];
    __shared__ __align__(16) float sC[NF_LOC][8];   // {C0e,C0o,C1e,C1o,C2e,C2o,-,-}

    const int b   = blockIdx.y;
    const int t0  = blockIdx.x * TS;
    const float* xb = x + (size_t)b * TLEN;
    const int base = t0 - 600;
    const bool eFirst = (blockIdx.x == 0);
    const bool eLast  = (blockIdx.x == gridDim.x - 1);
    const int tid = threadIdx.x;

    // Window table.
    for (int i = tid; i < N_FFT; i += blockDim.x)
        sw[i] = 0.5f - 0.5f * cosf((float)i * (float)(2.0 * PI_D / N_FFT));

    // Stage input (interior: base multiple of 4 -> float4 path).
    if (!(eFirst | eLast)) {
        const float4* __restrict__ src = (const float4*)(xb + base);
        float4* dst = (float4*)sx;
        for (int i = tid; i < SPAN / 4; i += blockDim.x)
            dst[i] = src[i];
    } else {
        for (int i = tid; i < SPAN; i += blockDim.x) {
            int idx = base + i;
            idx = idx < 0 ? 0 : (idx >= TLEN ? TLEN - 1 : idx);
            sx[i] = xb[idx];
        }
    }
    __syncthreads();

    // Phase 1: per hop block, three parity sums. EIGHT threads per hop block
    // (12 full warps; lanes with g>=NBLK run a clamped dummy so the group
    // shuffles stay fully converged). Thread j of block g accumulates the
    // stride-8 comb c = j, j+8, ... over 50 float4s, then a 3-step group
    // reduce (xor 1,2,4) combines the 8 partials.
    // Banks: word 200g+4(j+8k): within an LDS.128 phase-group (8 lanes,
    // same g) banks are 4j + const -> conflict-free.
    const float4* __restrict__ sw4 = (const float4*)sw;
    if (tid < 8 * 48) {                            // warps 0..11
        const int g0 = tid >> 3;
        const int g  = g0 < NBLK ? g0 : NBLK - 1;  // clamp dummies (g0 46,47)
        const int j  = tid & 7;
        const float4* __restrict__ xs = (const float4*)sx + g * (HOP / 4);
        float xe = 0.f, xo = 0.f, ae = 0.f, ao = 0.f, be = 0.f, bo = 0.f;
        #pragma unroll
        for (int k = 0; k < 7; k++) {
            const int c = j + 8 * k;
            if (c < HOP / 4) {
                const float4 v  = xs[c];
                const float4 wa = sw4[c];
                const float4 wb = sw4[c + HOP / 4];
                xe += v.x + v.z;                   xo += v.y + v.w;
                ae = fmaf(wa.x, v.x, fmaf(wa.z, v.z, ae));
                ao = fmaf(wa.y, v.y, fmaf(wa.w, v.w, ao));
                be = fmaf(wb.x, v.x, fmaf(wb.z, v.z, be));
                bo = fmaf(wb.y, v.y, fmaf(wb.w, v.w, bo));
            }
        }
        #pragma unroll
        for (int d = 1; d <= 4; d <<= 1) {
            xe += __shfl_xor_sync(0xffffffffu, xe, d);
            xo += __shfl_xor_sync(0xffffffffu, xo, d);
            ae += __shfl_xor_sync(0xffffffffu, ae, d);
            ao += __shfl_xor_sync(0xffffffffu, ao, d);
            be += __shfl_xor_sync(0xffffffffu, be, d);
            bo += __shfl_xor_sync(0xffffffffu, bo, d);
        }
        if (j == 0 && g0 < NBLK) {
            sX[g0][0] = xe; sX[g0][1] = xo;
            sA[g0][0] = ae; sA[g0][1] = ao;
            sB[g0][0] = be; sB[g0][1] = bo;
        }
    }
    __syncthreads();

    // Phase 1.5: packed per-frame-position combos (invalid frames -> S=0).
    const int f_base = t0 / HOP - 1;
    if (tid < 80) {                                // flq in [3, 43)
        const int flq = 3 + (tid >> 1), par = tid & 1;
        float s[4];                                // s[j] = S(flq - j)
        #pragma unroll
        for (int j = 0; j < 4; j++) {
            const int fl = flq - j;
            const int fg = fl + f_base;
            float v = sA[fl][par] + sB[fl + 1][par]
                    + (sX[fl + 2][par] - sA[fl + 2][par])
                    + (sX[fl + 3][par] - sB[fl + 3][par]);
            s[j] = (fg < 0 || fg >= N_FRAMES) ? 0.0f : v;
        }
        sC[flq][0 + par] = s[2] + s[3];            // C0
        sC[flq][2 + par] = s[0] - s[2];            // C1
        sC[flq][4 + par] = s[1] - s[3];            // C2
    }
    __syncthreads();

    // Phase 2: synthesis, 4 outputs per iteration, all-vector.
    float* __restrict__ ob = out + (size_t)b * TLEN + t0;
    const float4* __restrict__ sx4 = (const float4*)sx;
    for (int v = tid; v < TS / 4; v += blockDim.x) {
        const int u   = v + 100;                   // (4v + PAD)/4
        const int g   = u / 50;                    // q = t0/HOP + g
        const int r4  = u - g * 50;                // r0 = 4*r4
        const int flq = g + 1;
        const float4 xv = sx4[v + 150];
        const float4 w0 = sw4[r4];
        const float4 w1 = sw4[r4 + 50];
        const float4 cA = *(const float4*)&sC[flq][0];   // C0e,C0o,C1e,C1o
        const float4 cB = *(const float4*)&sC[flq][4];   // C2e,C2o,-,-
        float4 o;   // parities: x,z even; y,w odd
        o.x = fmaf(0.75f, xv.x, fmaf(w1.x, cB.x, fmaf(w0.x, cA.z, cA.x)) * (1.0f / 800.0f));
        o.y = fmaf(0.75f, xv.y, fmaf(w1.y, cB.y, fmaf(w0.y, cA.w, cA.y)) * (1.0f / 800.0f));
        o.z = fmaf(0.75f, xv.z, fmaf(w1.z, cB.x, fmaf(w0.z, cA.z, cA.x)) * (1.0f / 800.0f));
        o.w = fmaf(0.75f, xv.w, fmaf(w1.w, cB.y, fmaf(w0.w, cA.w, cA.y)) * (1.0f / 800.0f));
        // Boundary wsq correction (first/last 50 quads of edge tiles only):
        // missing frame j=3 at signal start (window r+600), j=0 at end (window r).
        if (eFirst && v < 50) {
            const float4 w3 = sw4[r4 + 150];
            o.x = fmaf(-0.5f * w3.x * w3.x, xv.x, o.x);
            o.y = fmaf(-0.5f * w3.y * w3.y, xv.y, o.y);
            o.z = fmaf(-0.5f * w3.z * w3.z, xv.z, o.z);
            o.w = fmaf(-0.5f * w3.w * w3.w, xv.w, o.w);
        }
        if (eLast && v >= TS / 4 - 50) {
            o.x = fmaf(-0.5f * w0.x * w0.x, xv.x, o.x);
            o.y = fmaf(-0.5f * w0.y * w0.y, xv.y, o.y);
            o.z = fmaf(-0.5f * w0.z * w0.z, xv.z, o.z);
            o.w = fmaf(-0.5f * w0.w * w0.w, xv.w, o.w);
        }
        *(float4*)&ob[4 * v] = o;
    }
}

extern "C" void kernel_launch(void* const* d_in, const int* in_sizes, int n_in,
                              void* d_out, int out_size) {
    const float* x = (const float*)d_in[0];
    float* out = (float*)d_out;

    dim3 grid(TLEN / TS, BATCH);       // 60 x 32 = 1920 blocks
    stft_fused_kernel<<<grid, 1024>>>(x, out);
}

// round 11
// speedup vs baseline: 1.0238x; 1.0238x over previous
#include <cuda_runtime.h>

#define N_FFT    800
#define HOP      200
#define BATCH    32
#define TLEN     480000
#define PAD      400
#define N_FRAMES 2401                 // (480800 - 800)/200 + 1
#define TS       8000                 // output tile per block
#define NF_LOC   (TS / HOP + 3)       // 43 frame positions per tile
#define NBLK     (TS / HOP + 6)       // 46 hop blocks feed those frames
#define SPAN     (TS + 1200)          // staged input: [t0-600, t0+TS+600)
#define NTHR     512

#define PI_D 3.14159265358979323846

// Fully fused STFT->mag/phase->iSTFT (linear-collapse derivation, R3/R6).
//   Hann identities: win(r+400)=1-win(r), win(r+600)=1-win(r+200),
//   sum_j win(r+200j)^2 = 1.5 exactly.
//   Per hop block g: X=sum(x), A=sum(win(r)x), B=sum(win(r+200)x) (per parity).
//   S[f] = A[f] + B[f+1] + (X[f+2]-A[f+2]) + (X[f+3]-B[f+3]).
//   out = 0.75*x + (C0 + win(r)*C1 + win(r+200)*C2)/800,
//     C0=S[q-2]+S[q-3], C1=S[q]-S[q-2], C2=S[q-1]-S[q-3]  (per parity).
//   Boundary (missing frame j at edge): out -= 0.5*x*win(r+200j)^2, S:=0.
__global__ __launch_bounds__(NTHR, 4)
void stft_fused_kernel(const float* __restrict__ x, float* __restrict__ out) {
    __shared__ __align__(16) float sx[SPAN];        // staged (clamped) input
    __shared__ __align__(16) float sw[N_FFT];       // Hann window
    __shared__ float sX[NBLK][2], sA[NBLK][2], sB[NBLK][2];
    __shared__ __align__(16) float sC[NF_LOC][8];   // {C0e,C0o,C1e,C1o,C2e,C2o,-,-}

    const int b   = blockIdx.y;
    const int t0  = blockIdx.x * TS;
    const float* xb = x + (size_t)b * TLEN;
    const int base = t0 - 600;
    const bool eFirst = (blockIdx.x == 0);
    const bool eLast  = (blockIdx.x == gridDim.x - 1);
    const int tid = threadIdx.x;

    // Window table (fast cos: abs err ~1e-6, 1000x under the 1e-3 gate).
    for (int i = tid; i < N_FFT; i += NTHR)
        sw[i] = 0.5f - 0.5f * __cosf((float)i * (float)(2.0 * PI_D / N_FFT));

    // Stage input (interior: base multiple of 4 -> float4 path).
    if (!(eFirst | eLast)) {
        const float4* __restrict__ src = (const float4*)(xb + base);
        float4* dst = (float4*)sx;
        for (int i = tid; i < SPAN / 4; i += NTHR)
            dst[i] = src[i];
    } else {
        for (int i = tid; i < SPAN; i += NTHR) {
            int idx = base + i;
            idx = idx < 0 ? 0 : (idx >= TLEN ? TLEN - 1 : idx);
            sx[i] = xb[idx];
        }
    }
    __syncthreads();

    // Phase 1: per hop block, three parity sums. FOUR threads per hop block
    // (tid < 192; tids 184-191 run a clamped dummy so group shuffles stay
    // converged). Thread j of block g accumulates the stride-4 comb
    // c = j, j+4, ..., then a 2-step group reduce (xor 1,2).
    const float4* __restrict__ sw4 = (const float4*)sw;
    if (tid < 4 * 48) {                            // warps 0..5
        const int g0 = tid >> 2;
        const int g  = g0 < NBLK ? g0 : NBLK - 1;  // clamp dummies (g0 46,47)
        const int j  = tid & 3;
        const float4* __restrict__ xs = (const float4*)sx + g * (HOP / 4);
        float xe = 0.f, xo = 0.f, ae = 0.f, ao = 0.f, be = 0.f, bo = 0.f;
        #pragma unroll
        for (int k = 0; k < 13; k++) {
            const int c = j + 4 * k;
            if (c < HOP / 4) {                     // only k=12 partially off
                const float4 v  = xs[c];
                const float4 wa = sw4[c];
                const float4 wb = sw4[c + HOP / 4];
                xe += v.x + v.z;                   xo += v.y + v.w;
                ae = fmaf(wa.x, v.x, fmaf(wa.z, v.z, ae));
                ao = fmaf(wa.y, v.y, fmaf(wa.w, v.w, ao));
                be = fmaf(wb.x, v.x, fmaf(wb.z, v.z, be));
                bo = fmaf(wb.y, v.y, fmaf(wb.w, v.w, bo));
            }
        }
        #pragma unroll
        for (int d = 1; d <= 2; d <<= 1) {
            xe += __shfl_xor_sync(0xffffffffu, xe, d);
            xo += __shfl_xor_sync(0xffffffffu, xo, d);
            ae += __shfl_xor_sync(0xffffffffu, ae, d);
            ao += __shfl_xor_sync(0xffffffffu, ao, d);
            be += __shfl_xor_sync(0xffffffffu, be, d);
            bo += __shfl_xor_sync(0xffffffffu, bo, d);
        }
        if (j == 0 && g0 < NBLK) {
            sX[g0][0] = xe; sX[g0][1] = xo;
            sA[g0][0] = ae; sA[g0][1] = ao;
            sB[g0][0] = be; sB[g0][1] = bo;
        }
    }
    __syncthreads();

    // Phase 1.5: packed per-frame-position combos (invalid frames -> S=0).
    const int f_base = t0 / HOP - 1;
    if (tid < 80) {                                // flq in [3, 43)
        const int flq = 3 + (tid >> 1), par = tid & 1;
        float s[4];                                // s[j] = S(flq - j)
        #pragma unroll
        for (int j = 0; j < 4; j++) {
            const int fl = flq - j;
            const int fg = fl + f_base;
            float v = sA[fl][par] + sB[fl + 1][par]
                    + (sX[fl + 2][par] - sA[fl + 2][par])
                    + (sX[fl + 3][par] - sB[fl + 3][par]);
            s[j] = (fg < 0 || fg >= N_FRAMES) ? 0.0f : v;
        }
        sC[flq][0 + par] = s[2] + s[3];            // C0
        sC[flq][2 + par] = s[0] - s[2];            // C1
        sC[flq][4 + par] = s[1] - s[3];            // C2
    }
    __syncthreads();

    // Phase 2: synthesis, 4 outputs per iteration, all-vector.
    float* __restrict__ ob = out + (size_t)b * TLEN + t0;
    const float4* __restrict__ sx4 = (const float4*)sx;
    for (int v = tid; v < TS / 4; v += NTHR) {
        const int u   = v + 100;                   // (4v + PAD)/4
        const int g   = u / 50;                    // q = t0/HOP + g
        const int r4  = u - g * 50;                // r0 = 4*r4
        const int flq = g + 1;
        const float4 xv = sx4[v + 150];
        const float4 w0 = sw4[r4];
        const float4 w1 = sw4[r4 + 50];
        const float4 cA = *(const float4*)&sC[flq][0];   // C0e,C0o,C1e,C1o
        const float4 cB = *(const float4*)&sC[flq][4];   // C2e,C2o,-,-
        float4 o;   // parities: x,z even; y,w odd
        o.x = fmaf(0.75f, xv.x, fmaf(w1.x, cB.x, fmaf(w0.x, cA.z, cA.x)) * (1.0f / 800.0f));
        o.y = fmaf(0.75f, xv.y, fmaf(w1.y, cB.y, fmaf(w0.y, cA.w, cA.y)) * (1.0f / 800.0f));
        o.z = fmaf(0.75f, xv.z, fmaf(w1.z, cB.x, fmaf(w0.z, cA.z, cA.x)) * (1.0f / 800.0f));
        o.w = fmaf(0.75f, xv.w, fmaf(w1.w, cB.y, fmaf(w0.w, cA.w, cA.y)) * (1.0f / 800.0f));
        // Boundary wsq correction (first/last 50 quads of edge tiles only):
        // missing frame j=3 at signal start (window r+600), j=0 at end (window r).
        if (eFirst && v < 50) {
            const float4 w3 = sw4[r4 + 150];
            o.x = fmaf(-0.5f * w3.x * w3.x, xv.x, o.x);
            o.y = fmaf(-0.5f * w3.y * w3.y, xv.y, o.y);
            o.z = fmaf(-0.5f * w3.z * w3.z, xv.z, o.z);
            o.w = fmaf(-0.5f * w3.w * w3.w, xv.w, o.w);
        }
        if (eLast && v >= TS / 4 - 50) {
            o.x = fmaf(-0.5f * w0.x * w0.x, xv.x, o.x);
            o.y = fmaf(-0.5f * w0.y * w0.y, xv.y, o.y);
            o.z = fmaf(-0.5f * w0.z * w0.z, xv.z, o.z);
            o.w = fmaf(-0.5f * w0.w * w0.w, xv.w, o.w);
        }
        *(float4*)&ob[4 * v] = o;
    }
}

extern "C" void kernel_launch(void* const* d_in, const int* in_sizes, int n_in,
                              void* d_out, int out_size) {
    const float* x = (const float*)d_in[0];
    float* out = (float*)d_out;

    dim3 grid(TLEN / TS, BATCH);       // 60 x 32 = 1920 blocks
    stft_fused_kernel<<<grid, NTHR>>>(x, out);
}

// round 12
// speedup vs baseline: 1.2403x; 1.2115x over previous
#include <cuda_runtime.h>

#define N_FFT    800
#define HOP      200
#define BATCH    32
#define TLEN     480000
#define PAD      400
#define N_FRAMES 2401                 // frames per batch
#define NHOP     2404                 // hop blocks per batch: 480800/200
#define AOUT     64                   // C outputs (q positions) per A-block
#define AHOPS    (AOUT + 6)           // computed hop sums incl. 3+3 halo
#define NQUAD    (TLEN / 4)           // 120000 output quads per batch

#define PI_D 3.14159265358979323846

// Fully fused STFT->mag/phase->iSTFT (linear-collapse derivation, R3/R6):
//   Hann identities: win(r+400)=1-win(r), win(r+600)=1-win(r+200),
//   sum_j win(r+200j)^2 = 1.5 exactly.
//   Per hop block g: X=sum(x), A=sum(win(r)x), B=sum(win(r+200)x) (per parity).
//   S[f] = A[f] + B[f+1] + (X[f+2]-A[f+2]) + (X[f+3]-B[f+3]);  S=0 off-range.
//   out = 0.75*x + (C0 + win(r)*C1 + win(r+200)*C2)/800,
//     C0=S[q-2]+S[q-3], C1=S[q]-S[q-2], C2=S[q-1]-S[q-3]  (per parity).
//   Missing frame j at signal edge additionally: out -= 0.5*x*win(r+200j)^2.
//
// Two-kernel split: A computes C combos into global scratch; B is a pure
// barrier-light stream: x (LDG) + C (broadcast LDG) + window (LDS) -> out.

__device__ float gC[BATCH][NHOP][8];   // {C0e,C0o,C1e,C1o,C2e,C2o,0,0}

// ---------------- Kernel A: hop sums + C combos ----------------
__global__ __launch_bounds__(288, 4)
void sums_kernel(const float* __restrict__ x) {
    __shared__ __align__(16) float sw[400];       // win[0..400)
    __shared__ float sXAB[AHOPS][6];              // {Xe,Xo,Ae,Ao,Be,Bo}

    const int b   = blockIdx.y;
    const int Q0  = blockIdx.x * AOUT;
    const int tid = threadIdx.x;
    const float* __restrict__ xb = x + (size_t)b * TLEN;

    for (int i = tid; i < 400; i += 288)
        sw[i] = 0.5f - 0.5f * __cosf((float)i * (float)(2.0 * PI_D / N_FFT));
    __syncthreads();

    // 4 threads per hop block; groups 70,71 are converged dummies.
    const int grp = tid >> 2;
    const int j   = tid & 3;
    const int gh  = Q0 - 3 + (grp < AHOPS ? grp : AHOPS - 1);
    const float4* __restrict__ sw4 = (const float4*)sw;

    float xe = 0.f, xo = 0.f, ae = 0.f, ao = 0.f, be = 0.f, bo = 0.f;
    if (gh >= 2 && gh <= 2401) {
        // Interior: xp[200*gh + r] = x[200*gh + r - 400], all in range.
        const float4* __restrict__ xs = (const float4*)xb + (50 * gh - 100);
        #pragma unroll
        for (int k = 0; k < 13; k++) {
            const int c = j + 4 * k;
            if (c < 50) {
                const float4 v  = xs[c];
                const float4 wa = sw4[c];
                const float4 wb = sw4[c + 50];
                xe += v.x + v.z;                   xo += v.y + v.w;
                ae = fmaf(wa.x, v.x, fmaf(wa.z, v.z, ae));
                ao = fmaf(wa.y, v.y, fmaf(wa.w, v.w, ao));
                be = fmaf(wb.x, v.x, fmaf(wb.z, v.z, be));
                bo = fmaf(wb.y, v.y, fmaf(wb.w, v.w, bo));
            }
        }
    } else {
        // Edge hop blocks (only 0,1,2402,2403 + halo dummies): clamped scalar.
        #pragma unroll
        for (int k = 0; k < 13; k++) {
            const int c = j + 4 * k;
            if (c < 50) {
                const int r = 4 * c;
                #pragma unroll
                for (int e = 0; e < 4; e += 2) {
                    int p0 = 200 * gh + r + e - PAD;        // even element
                    int p1 = p0 + 1;                        // odd element
                    p0 = p0 < 0 ? 0 : (p0 >= TLEN ? TLEN - 1 : p0);
                    p1 = p1 < 0 ? 0 : (p1 >= TLEN ? TLEN - 1 : p1);
                    const float v0 = xb[p0], v1 = xb[p1];
                    xe += v0;                         xo += v1;
                    ae = fmaf(sw[r + e], v0, ae);     ao = fmaf(sw[r + e + 1], v1, ao);
                    be = fmaf(sw[r + e + 200], v0, be);
                    bo = fmaf(sw[r + e + 201], v1, bo);
                }
            }
        }
    }
    #pragma unroll
    for (int d = 1; d <= 2; d <<= 1) {
        xe += __shfl_xor_sync(0xffffffffu, xe, d);
        xo += __shfl_xor_sync(0xffffffffu, xo, d);
        ae += __shfl_xor_sync(0xffffffffu, ae, d);
        ao += __shfl_xor_sync(0xffffffffu, ao, d);
        be += __shfl_xor_sync(0xffffffffu, be, d);
        bo += __shfl_xor_sync(0xffffffffu, bo, d);
    }
    if (j == 0 && grp < AHOPS) {
        sXAB[grp][0] = xe; sXAB[grp][1] = xo;
        sXAB[grp][2] = ae; sXAB[grp][3] = ao;
        sXAB[grp][4] = be; sXAB[grp][5] = bo;
    }
    __syncthreads();

    // C combos for q = Q0 + ql, per parity. Invalid frames -> S = 0.
    if (tid < 2 * AOUT) {
        const int ql = tid >> 1, par = tid & 1;
        const int q  = Q0 + ql;
        if (q < NHOP) {
            float s[4];                           // s[jj] = S(q - jj)
            #pragma unroll
            for (int jj = 0; jj < 4; jj++) {
                const int f  = q - jj;
                const int fl = ql + 3 - jj;       // hop f local index
                const float v = sXAB[fl][2 + par] + sXAB[fl + 1][4 + par]
                              + (sXAB[fl + 2][par] - sXAB[fl + 2][2 + par])
                              + (sXAB[fl + 3][par] - sXAB[fl + 3][4 + par]);
                s[jj] = (f < 0 || f >= N_FRAMES) ? 0.0f : v;
            }
            float* __restrict__ cp = gC[b][q];
            cp[0 + par] = s[2] + s[3];            // C0
            cp[2 + par] = s[0] - s[2];            // C1
            cp[4 + par] = s[1] - s[3];            // C2
        }
    }
}

// ---------------- Kernel B: streaming synthesis ----------------
__global__ __launch_bounds__(256, 8)
void synth_kernel(const float* __restrict__ x, float* __restrict__ out) {
    __shared__ __align__(16) float sw[N_FFT];

    const int b   = blockIdx.y;
    const int tid = threadIdx.x;
    for (int i = tid; i < N_FFT; i += 256)
        sw[i] = 0.5f - 0.5f * __cosf((float)i * (float)(2.0 * PI_D / N_FFT));
    __syncthreads();

    const float4* __restrict__ sw4 = (const float4*)sw;
    const float4* __restrict__ x4  = (const float4*)(x + (size_t)b * TLEN);
    float4* __restrict__ o4        = (float4*)(out + (size_t)b * TLEN);
    const int V0 = blockIdx.x * 1024;

    #pragma unroll
    for (int k = 0; k < 4; k++) {
        const int v = V0 + tid + 256 * k;
        if (v < NQUAD) {
            const int u  = v + 100;               // (4v + PAD)/4
            const int q  = u / 50;                // frame position
            const int r4 = u - 50 * q;            // r = 4*r4
            const float4 xv = x4[v];
            const float4 w0 = sw4[r4];
            const float4 w1 = sw4[r4 + 50];
            const float* __restrict__ cp = gC[b][q];
            const float4 cA = *(const float4*)cp;        // C0e,C0o,C1e,C1o
            const float4 cB = *(const float4*)(cp + 4);  // C2e,C2o,0,0
            float4 o;   // parities: x,z even; y,w odd
            o.x = fmaf(0.75f, xv.x, fmaf(w1.x, cB.x, fmaf(w0.x, cA.z, cA.x)) * (1.0f / 800.0f));
            o.y = fmaf(0.75f, xv.y, fmaf(w1.y, cB.y, fmaf(w0.y, cA.w, cA.y)) * (1.0f / 800.0f));
            o.z = fmaf(0.75f, xv.z, fmaf(w1.z, cB.x, fmaf(w0.z, cA.z, cA.x)) * (1.0f / 800.0f));
            o.w = fmaf(0.75f, xv.w, fmaf(w1.w, cB.y, fmaf(w0.w, cA.w, cA.y)) * (1.0f / 800.0f));
            // Edge wsq corrections (first/last 50 quads of each batch).
            if (v < 50) {                         // missing frame j=3 (win r+600)
                const float4 w3 = sw4[r4 + 150];
                o.x = fmaf(-0.5f * w3.x * w3.x, xv.x, o.x);
                o.y = fmaf(-0.5f * w3.y * w3.y, xv.y, o.y);
                o.z = fmaf(-0.5f * w3.z * w3.z, xv.z, o.z);
                o.w = fmaf(-0.5f * w3.w * w3.w, xv.w, o.w);
            }
            if (v >= NQUAD - 50) {                // missing frame j=0 (win r)
                o.x = fmaf(-0.5f * w0.x * w0.x, xv.x, o.x);
                o.y = fmaf(-0.5f * w0.y * w0.y, xv.y, o.y);
                o.z = fmaf(-0.5f * w0.z * w0.z, xv.z, o.z);
                o.w = fmaf(-0.5f * w0.w * w0.w, xv.w, o.w);
            }
            o4[v] = o;
        }
    }
}

extern "C" void kernel_launch(void* const* d_in, const int* in_sizes, int n_in,
                              void* d_out, int out_size) {
    const float* x = (const float*)d_in[0];
    float* out = (float*)d_out;

    dim3 gridA((NHOP + AOUT - 1) / AOUT, BATCH);      // 38 x 32
    sums_kernel<<<gridA, 288>>>(x);

    dim3 gridB((NQUAD + 1023) / 1024, BATCH);         // 118 x 32
    synth_kernel<<<gridB, 256>>>(x, out);
}